// round 1
// baseline (speedup 1.0000x reference)
#include <cuda_runtime.h>

#define BB 2
#define NTOK 256
#define DD 512
#define HH 2048
#define MM (BB*NTOK)   /* 512 rows total */

// ---------------- scratch (device globals: allocation-free) ----------------
__device__ float g_xvw[BB*NTOK*DD];     // weighted x_v
__device__ float g_xaw[BB*NTOK*DD];     // weighted x_a
__device__ float g_h1v[MM*HH];          // gelu(xv_w @ W1v + b1v)
__device__ float g_h1a[MM*HH];
__device__ float g_comb[MM*2*DD];       // [hv | ha]

// ---------------- packed fp32x2 helpers (SASS FFMA2 path) ----------------
__device__ __forceinline__ unsigned long long pack_dup2(float a){
    unsigned int ua = __float_as_uint(a);
    unsigned long long r;
    asm("mov.b64 %0, {%1, %1};" : "=l"(r) : "r"(ua));
    return r;
}
__device__ __forceinline__ unsigned long long fma_f32x2(unsigned long long a,
                                                        unsigned long long b,
                                                        unsigned long long c){
    unsigned long long d;
    asm("fma.rn.f32x2 %0, %1, %2, %3;" : "=l"(d) : "l"(a), "l"(b), "l"(c));
    return d;
}
__device__ __forceinline__ float2 unpack2(unsigned long long v){
    unsigned int lo, hi;
    asm("mov.b64 {%0, %1}, %2;" : "=r"(lo), "=r"(hi) : "l"(v));
    return make_float2(__uint_as_float(lo), __uint_as_float(hi));
}

// ---------------------------------------------------------------------------
// Distance + weighting kernel.
// dist(i,j) = sum_d |xv[b,i,d] - xa[b,j,d]|
// dv[b,i] = mean_j dist(i,j);  da[b,j] = mean_i dist(i,j)
// blockIdx.z = 0: self=xv (produce xvw);  = 1: self=xa (produce xaw).
// Each block handles 4 "self" rows (kept in registers), streams all 256
// "other" rows (L2-resident), block-reduces, writes weighted self rows.
// ---------------------------------------------------------------------------
__global__ void __launch_bounds__(128)
dist_weight_dual(const float* __restrict__ xv, const float* __restrict__ xa,
                 float* __restrict__ xvw, float* __restrict__ xaw)
{
    const int dir = blockIdx.z;
    const float* self  = dir ? xa : xv;
    const float* other = dir ? xv : xa;
    float* outp        = dir ? xaw : xvw;

    const int b  = blockIdx.y;
    const int i0 = blockIdx.x * 4;
    const int t  = threadIdx.x;          // 128 threads, each owns one float4 slice

    const float4* sbase = reinterpret_cast<const float4*>(self  + (size_t)b*NTOK*DD);
    const float4* obase = reinterpret_cast<const float4*>(other + (size_t)b*NTOK*DD);

    const float4 a0 = sbase[(size_t)(i0+0)*128 + t];
    const float4 a1 = sbase[(size_t)(i0+1)*128 + t];
    const float4 a2 = sbase[(size_t)(i0+2)*128 + t];
    const float4 a3 = sbase[(size_t)(i0+3)*128 + t];

    float c0 = 0.f, c1 = 0.f, c2 = 0.f, c3 = 0.f;
    #pragma unroll 4
    for (int j = 0; j < NTOK; ++j){
        const float4 o = obase[(size_t)j*128 + t];
        c0 += fabsf(a0.x-o.x) + fabsf(a0.y-o.y) + fabsf(a0.z-o.z) + fabsf(a0.w-o.w);
        c1 += fabsf(a1.x-o.x) + fabsf(a1.y-o.y) + fabsf(a1.z-o.z) + fabsf(a1.w-o.w);
        c2 += fabsf(a2.x-o.x) + fabsf(a2.y-o.y) + fabsf(a2.z-o.z) + fabsf(a2.w-o.w);
        c3 += fabsf(a3.x-o.x) + fabsf(a3.y-o.y) + fabsf(a3.z-o.z) + fabsf(a3.w-o.w);
    }

    __shared__ float red[4][128];
    red[0][t] = c0; red[1][t] = c1; red[2][t] = c2; red[3][t] = c3;
    __syncthreads();
    for (int s = 64; s > 0; s >>= 1){
        if (t < s){
            red[0][t] += red[0][t+s];
            red[1][t] += red[1][t+s];
            red[2][t] += red[2][t+s];
            red[3][t] += red[3][t+s];
        }
        __syncthreads();
    }

    const float inv = 1.0f / (float)NTOK;
    const float s0 = red[0][0]*inv, s1 = red[1][0]*inv;
    const float s2 = red[2][0]*inv, s3 = red[3][0]*inv;

    float4* ob = reinterpret_cast<float4*>(outp + (size_t)b*NTOK*DD);
    ob[(size_t)(i0+0)*128 + t] = make_float4(a0.x*s0, a0.y*s0, a0.z*s0, a0.w*s0);
    ob[(size_t)(i0+1)*128 + t] = make_float4(a1.x*s1, a1.y*s1, a1.z*s1, a1.w*s1);
    ob[(size_t)(i0+2)*128 + t] = make_float4(a2.x*s2, a2.y*s2, a2.z*s2, a2.w*s2);
    ob[(size_t)(i0+3)*128 + t] = make_float4(a3.x*s3, a3.y*s3, a3.z*s3, a3.w*s3);
}

// ---------------------------------------------------------------------------
// fp32 SGEMM core: C[M,N] = A[M,K] @ B[K,N] + bias, optional exact-erf GELU.
// BM=BN=64, BK=16, 256 threads, 4x4 microtile, FFMA2 (fp32x2) accumulation.
// All problem dims divide the tiles exactly -> no bounds checks.
// ---------------------------------------------------------------------------
__device__ __forceinline__ void sgemm_core(
    const float* __restrict__ A, const float* __restrict__ B,
    const float* __restrict__ bias, float* __restrict__ C,
    int K, int N, int ldc, int coloff, int gelu)
{
    constexpr int BM = 64, BN = 64, BK = 16;
    __shared__ float As[BK][BM + 4];   // As[k][m]; +4 pad (row stride 272B, 16B-aligned)
    __shared__ float Bs[BK][BN];

    const int t  = threadIdx.x;        // 256
    const int tx = t & 15;
    const int ty = t >> 4;
    const int m0 = blockIdx.y * BM;
    const int n0 = blockIdx.x * BN;

    // A tile load mapping: each thread grabs 4 consecutive K from one row
    const int a_row = t >> 2;          // 0..63
    const int a_kq  = (t & 3) << 2;    // 0,4,8,12
    // B tile load mapping: each thread grabs float4 along N
    const int b_kk  = t >> 4;          // 0..15
    const int b_n   = (t & 15) << 2;   // 0..60

    const float* Aload = A + (size_t)(m0 + a_row)*K + a_kq;
    const float* Bload = B + (size_t)b_kk*N + n0 + b_n;

    unsigned long long acc[4][2];
    #pragma unroll
    for (int r = 0; r < 4; ++r){ acc[r][0] = 0ull; acc[r][1] = 0ull; }

    for (int k0 = 0; k0 < K; k0 += BK){
        const float4 av = *reinterpret_cast<const float4*>(Aload + k0);
        const float4 bv = *reinterpret_cast<const float4*>(Bload + (size_t)k0*N);
        As[a_kq+0][a_row] = av.x;
        As[a_kq+1][a_row] = av.y;
        As[a_kq+2][a_row] = av.z;
        As[a_kq+3][a_row] = av.w;
        *reinterpret_cast<float4*>(&Bs[b_kk][b_n]) = bv;
        __syncthreads();

        #pragma unroll
        for (int kk = 0; kk < BK; ++kk){
            const float4 a4 = *reinterpret_cast<const float4*>(&As[kk][ty << 2]);
            const unsigned long long b01 =
                *reinterpret_cast<const unsigned long long*>(&Bs[kk][tx << 2]);
            const unsigned long long b23 =
                *reinterpret_cast<const unsigned long long*>(&Bs[kk][(tx << 2) + 2]);
            const unsigned long long ax = pack_dup2(a4.x);
            const unsigned long long ay = pack_dup2(a4.y);
            const unsigned long long az = pack_dup2(a4.z);
            const unsigned long long aw = pack_dup2(a4.w);
            acc[0][0] = fma_f32x2(ax, b01, acc[0][0]);
            acc[0][1] = fma_f32x2(ax, b23, acc[0][1]);
            acc[1][0] = fma_f32x2(ay, b01, acc[1][0]);
            acc[1][1] = fma_f32x2(ay, b23, acc[1][1]);
            acc[2][0] = fma_f32x2(az, b01, acc[2][0]);
            acc[2][1] = fma_f32x2(az, b23, acc[2][1]);
            acc[3][0] = fma_f32x2(aw, b01, acc[3][0]);
            acc[3][1] = fma_f32x2(aw, b23, acc[3][1]);
        }
        __syncthreads();
    }

    // epilogue: bias (+GELU) + vectorized store
    const int colbase = n0 + (tx << 2);
    const float bb0 = bias[colbase+0];
    const float bb1 = bias[colbase+1];
    const float bb2 = bias[colbase+2];
    const float bb3 = bias[colbase+3];
    #pragma unroll
    for (int r = 0; r < 4; ++r){
        const int row = m0 + (ty << 2) + r;
        const float2 v01 = unpack2(acc[r][0]);
        const float2 v23 = unpack2(acc[r][1]);
        float v0 = v01.x + bb0;
        float v1 = v01.y + bb1;
        float v2 = v23.x + bb2;
        float v3 = v23.y + bb3;
        if (gelu){
            v0 = 0.5f*v0*(1.0f + erff(v0*0.70710678118654752f));
            v1 = 0.5f*v1*(1.0f + erff(v1*0.70710678118654752f));
            v2 = 0.5f*v2*(1.0f + erff(v2*0.70710678118654752f));
            v3 = 0.5f*v3*(1.0f + erff(v3*0.70710678118654752f));
        }
        *reinterpret_cast<float4*>(C + (size_t)row*ldc + coloff + colbase) =
            make_float4(v0, v1, v2, v3);
    }
}

__global__ void __launch_bounds__(256)
sgemm_single(const float* __restrict__ A, const float* __restrict__ B,
             const float* __restrict__ bias, float* __restrict__ C,
             int K, int N, int ldc, int coloff, int gelu)
{
    sgemm_core(A, B, bias, C, K, N, ldc, coloff, gelu);
}

// v/a fused via blockIdx.z (keeps the wave full for the 8x8-block GEMMs)
__global__ void __launch_bounds__(256)
sgemm_dual(const float* __restrict__ A0, const float* __restrict__ B0,
           const float* __restrict__ bi0, float* __restrict__ C0, int co0,
           const float* __restrict__ A1, const float* __restrict__ B1,
           const float* __restrict__ bi1, float* __restrict__ C1, int co1,
           int K, int N, int ldc, int gelu)
{
    if (blockIdx.z == 0) sgemm_core(A0, B0, bi0, C0, K, N, ldc, co0, gelu);
    else                 sgemm_core(A1, B1, bi1, C1, K, N, ldc, co1, gelu);
}

// ---------------------------------------------------------------------------
extern "C" void kernel_launch(void* const* d_in, const int* in_sizes, int n_in,
                              void* d_out, int out_size)
{
    (void)in_sizes; (void)n_in; (void)out_size;

    const float* x_v  = (const float*)d_in[0];
    const float* x_a  = (const float*)d_in[1];
    const float* W1v  = (const float*)d_in[2];
    const float* b1v  = (const float*)d_in[3];
    const float* W1a  = (const float*)d_in[4];
    const float* b1a  = (const float*)d_in[5];
    const float* Wmv  = (const float*)d_in[6];
    const float* bmv  = (const float*)d_in[7];
    const float* Wma  = (const float*)d_in[8];
    const float* bma  = (const float*)d_in[9];
    const float* Wout = (const float*)d_in[10];
    const float* bout = (const float*)d_in[11];
    float* out = (float*)d_out;

    float *xvw, *xaw, *h1v, *h1a, *comb;
    cudaGetSymbolAddress((void**)&xvw,  g_xvw);
    cudaGetSymbolAddress((void**)&xaw,  g_xaw);
    cudaGetSymbolAddress((void**)&h1v,  g_h1v);
    cudaGetSymbolAddress((void**)&h1a,  g_h1a);
    cudaGetSymbolAddress((void**)&comb, g_comb);

    // 1) pairwise L1 distances -> dv/da -> weighted inputs (both directions)
    dist_weight_dual<<<dim3(NTOK/4, BB, 2), 128>>>(x_v, x_a, xvw, xaw);

    // 2) h1 = gelu(xw @ W1 + b1)   [512 x 2048], v & a fused
    sgemm_dual<<<dim3(HH/64, MM/64, 2), 256>>>(
        xvw, W1v, b1v, h1v, 0,
        xaw, W1a, b1a, h1a, 0,
        DD, HH, HH, 1);

    // 3) h = h1 @ Wm + bm -> write straight into concat buffer [512 x 1024]
    sgemm_dual<<<dim3(DD/64, MM/64, 2), 256>>>(
        h1v, Wmv, bmv, comb, 0,
        h1a, Wma, bma, comb, DD,
        HH, DD, 2*DD, 0);

    // 4) out = comb @ Wout + bout   [512 x 512]
    sgemm_single<<<dim3(DD/64, MM/64), 256>>>(comb, Wout, bout, out,
                                              2*DD, DD, DD, 0, 0);
}

// round 2
// speedup vs baseline: 1.6737x; 1.6737x over previous
#include <cuda_runtime.h>

#define BB 2
#define NTOK 256
#define DD 512
#define HH 2048
#define MM (BB*NTOK)   /* 512 rows total */

typedef unsigned long long ull;

// ---------------- scratch (device globals: allocation-free) ----------------
__device__ float g_xvw[BB*NTOK*DD];       // weighted x_v
__device__ float g_xaw[BB*NTOK*DD];       // weighted x_a
__device__ float g_h1v[MM*HH];            // gelu(xv_w @ W1v + b1v)
__device__ float g_h1a[MM*HH];
__device__ float g_p2[2][2][MM*DD];       // G2 partials [side][ksplit]
__device__ float g_p3[4][MM*DD];          // G3 partials [ksplit]

// ---------------- packed fp32x2 helpers (SASS FFMA2 path) ----------------
__device__ __forceinline__ ull pack_dup2(float a){
    unsigned int ua = __float_as_uint(a);
    ull r;
    asm("mov.b64 %0, {%1, %1};" : "=l"(r) : "r"(ua));
    return r;
}
__device__ __forceinline__ ull fma_f32x2(ull a, ull b, ull c){
    ull d;
    asm("fma.rn.f32x2 %0, %1, %2, %3;" : "=l"(d) : "l"(a), "l"(b), "l"(c));
    return d;
}
__device__ __forceinline__ float2 unpack2(ull v){
    unsigned int lo, hi;
    asm("mov.b64 {%0, %1}, %2;" : "=r"(lo), "=r"(hi) : "l"(v));
    return make_float2(__uint_as_float(lo), __uint_as_float(hi));
}
__device__ __forceinline__ float gelu1(float x){
    return 0.5f*x*(1.0f + erff(x*0.70710678118654752f));
}

// ---------------------------------------------------------------------------
// Distance + weighting kernel (unchanged: ~11us, L2-resident streaming)
// ---------------------------------------------------------------------------
__global__ void __launch_bounds__(128)
dist_weight_dual(const float* __restrict__ xv, const float* __restrict__ xa,
                 float* __restrict__ xvw, float* __restrict__ xaw)
{
    const int dir = blockIdx.z;
    const float* self  = dir ? xa : xv;
    const float* other = dir ? xv : xa;
    float* outp        = dir ? xaw : xvw;

    const int b  = blockIdx.y;
    const int i0 = blockIdx.x * 4;
    const int t  = threadIdx.x;

    const float4* sbase = reinterpret_cast<const float4*>(self  + (size_t)b*NTOK*DD);
    const float4* obase = reinterpret_cast<const float4*>(other + (size_t)b*NTOK*DD);

    const float4 a0 = sbase[(size_t)(i0+0)*128 + t];
    const float4 a1 = sbase[(size_t)(i0+1)*128 + t];
    const float4 a2 = sbase[(size_t)(i0+2)*128 + t];
    const float4 a3 = sbase[(size_t)(i0+3)*128 + t];

    float c0 = 0.f, c1 = 0.f, c2 = 0.f, c3 = 0.f;
    #pragma unroll 4
    for (int j = 0; j < NTOK; ++j){
        const float4 o = obase[(size_t)j*128 + t];
        c0 += fabsf(a0.x-o.x) + fabsf(a0.y-o.y) + fabsf(a0.z-o.z) + fabsf(a0.w-o.w);
        c1 += fabsf(a1.x-o.x) + fabsf(a1.y-o.y) + fabsf(a1.z-o.z) + fabsf(a1.w-o.w);
        c2 += fabsf(a2.x-o.x) + fabsf(a2.y-o.y) + fabsf(a2.z-o.z) + fabsf(a2.w-o.w);
        c3 += fabsf(a3.x-o.x) + fabsf(a3.y-o.y) + fabsf(a3.z-o.z) + fabsf(a3.w-o.w);
    }

    __shared__ float red[4][128];
    red[0][t] = c0; red[1][t] = c1; red[2][t] = c2; red[3][t] = c3;
    __syncthreads();
    for (int s = 64; s > 0; s >>= 1){
        if (t < s){
            red[0][t] += red[0][t+s];
            red[1][t] += red[1][t+s];
            red[2][t] += red[2][t+s];
            red[3][t] += red[3][t+s];
        }
        __syncthreads();
    }

    const float inv = 1.0f / (float)NTOK;
    const float s0 = red[0][0]*inv, s1 = red[1][0]*inv;
    const float s2 = red[2][0]*inv, s3 = red[3][0]*inv;

    float4* ob = reinterpret_cast<float4*>(outp + (size_t)b*NTOK*DD);
    ob[(size_t)(i0+0)*128 + t] = make_float4(a0.x*s0, a0.y*s0, a0.z*s0, a0.w*s0);
    ob[(size_t)(i0+1)*128 + t] = make_float4(a1.x*s1, a1.y*s1, a1.z*s1, a1.w*s1);
    ob[(size_t)(i0+2)*128 + t] = make_float4(a2.x*s2, a2.y*s2, a2.z*s2, a2.w*s2);
    ob[(size_t)(i0+3)*128 + t] = make_float4(a3.x*s3, a3.y*s3, a3.z*s3, a3.w*s3);
}

// ---------------------------------------------------------------------------
// Microtile compute: 8x8 outputs/thread as acc[8][4] f32x2 pairs.
// B fragments: u64 indices tx, 16+tx, 32+tx, 48+tx within a 128-float row
// -> conflict-free LDS.64 (half-warp covers 128B contiguously), no B packing.
// A fragments: broadcast LDS.128 (2 distinct addrs/warp).
// ---------------------------------------------------------------------------
#define INNER_KK(As_row, Bs_row, ACC)                                         \
    {                                                                         \
        const float4 _a0 = *reinterpret_cast<const float4*>(&(As_row)[ty*4]); \
        const float4 _a1 = *reinterpret_cast<const float4*>(&(As_row)[A_HI + ty*4]); \
        const ull* _bu = reinterpret_cast<const ull*>(Bs_row);                \
        const ull _b0 = _bu[tx];                                              \
        const ull _b1 = _bu[16 + tx];                                         \
        const ull _b2 = _bu[32 + tx];                                         \
        const ull _b3 = _bu[48 + tx];                                         \
        ull _p;                                                               \
        _p = pack_dup2(_a0.x);                                                \
        ACC[0][0]=fma_f32x2(_p,_b0,ACC[0][0]); ACC[0][1]=fma_f32x2(_p,_b1,ACC[0][1]); \
        ACC[0][2]=fma_f32x2(_p,_b2,ACC[0][2]); ACC[0][3]=fma_f32x2(_p,_b3,ACC[0][3]); \
        _p = pack_dup2(_a0.y);                                                \
        ACC[1][0]=fma_f32x2(_p,_b0,ACC[1][0]); ACC[1][1]=fma_f32x2(_p,_b1,ACC[1][1]); \
        ACC[1][2]=fma_f32x2(_p,_b2,ACC[1][2]); ACC[1][3]=fma_f32x2(_p,_b3,ACC[1][3]); \
        _p = pack_dup2(_a0.z);                                                \
        ACC[2][0]=fma_f32x2(_p,_b0,ACC[2][0]); ACC[2][1]=fma_f32x2(_p,_b1,ACC[2][1]); \
        ACC[2][2]=fma_f32x2(_p,_b2,ACC[2][2]); ACC[2][3]=fma_f32x2(_p,_b3,ACC[2][3]); \
        _p = pack_dup2(_a0.w);                                                \
        ACC[3][0]=fma_f32x2(_p,_b0,ACC[3][0]); ACC[3][1]=fma_f32x2(_p,_b1,ACC[3][1]); \
        ACC[3][2]=fma_f32x2(_p,_b2,ACC[3][2]); ACC[3][3]=fma_f32x2(_p,_b3,ACC[3][3]); \
        _p = pack_dup2(_a1.x);                                                \
        ACC[4][0]=fma_f32x2(_p,_b0,ACC[4][0]); ACC[4][1]=fma_f32x2(_p,_b1,ACC[4][1]); \
        ACC[4][2]=fma_f32x2(_p,_b2,ACC[4][2]); ACC[4][3]=fma_f32x2(_p,_b3,ACC[4][3]); \
        _p = pack_dup2(_a1.y);                                                \
        ACC[5][0]=fma_f32x2(_p,_b0,ACC[5][0]); ACC[5][1]=fma_f32x2(_p,_b1,ACC[5][1]); \
        ACC[5][2]=fma_f32x2(_p,_b2,ACC[5][2]); ACC[5][3]=fma_f32x2(_p,_b3,ACC[5][3]); \
        _p = pack_dup2(_a1.z);                                                \
        ACC[6][0]=fma_f32x2(_p,_b0,ACC[6][0]); ACC[6][1]=fma_f32x2(_p,_b1,ACC[6][1]); \
        ACC[6][2]=fma_f32x2(_p,_b2,ACC[6][2]); ACC[6][3]=fma_f32x2(_p,_b3,ACC[6][3]); \
        _p = pack_dup2(_a1.w);                                                \
        ACC[7][0]=fma_f32x2(_p,_b0,ACC[7][0]); ACC[7][1]=fma_f32x2(_p,_b1,ACC[7][1]); \
        ACC[7][2]=fma_f32x2(_p,_b2,ACC[7][2]); ACC[7][3]=fma_f32x2(_p,_b3,ACC[7][3]); \
    }

// ---------------------------------------------------------------------------
// gemm128: BM=BN=128, BK=16, 256 threads, 8x8 micro; v/a fused via blockIdx.z.
// Used for G1 (gelu epilogue). grid = (N/128, M/128, 2).
// ---------------------------------------------------------------------------
__global__ void __launch_bounds__(256)
gemm128_dual(const float* __restrict__ A0, const float* __restrict__ B0,
             const float* __restrict__ bi0, float* __restrict__ C0,
             const float* __restrict__ A1, const float* __restrict__ B1,
             const float* __restrict__ bi1, float* __restrict__ C1,
             int K, int N)
{
    const float* A    = blockIdx.z ? A1 : A0;
    const float* B    = blockIdx.z ? B1 : B0;
    const float* bias = blockIdx.z ? bi1 : bi0;
    float*       C    = blockIdx.z ? C1 : C0;

    constexpr int A_HI = 64;
    __shared__ float As[16][132];   // [k][m], 132*4B = 16B-aligned rows
    __shared__ float Bs[16][128];

    const int t  = threadIdx.x;
    const int tx = t & 15;
    const int ty = t >> 4;
    const int m0 = blockIdx.y * 128;
    const int n0 = blockIdx.x * 128;

    const int ar  = t >> 2;          // 0..63
    const int akq = (t & 3) << 2;    // 0,4,8,12
    const float* Ap0 = A + (size_t)(m0 + ar)*K + akq;
    const float* Ap1 = Ap0 + (size_t)64*K;
    const int bkk = t >> 4;          // 0..15
    const int bnc = (t & 15) << 2;   // 0..60
    const float* Bp0 = B + (size_t)bkk*N + n0 + bnc;
    const float* Bp1 = Bp0 + 64;

    float4 ra0 = *reinterpret_cast<const float4*>(Ap0);
    float4 ra1 = *reinterpret_cast<const float4*>(Ap1);
    float4 rb0 = *reinterpret_cast<const float4*>(Bp0);
    float4 rb1 = *reinterpret_cast<const float4*>(Bp1);

    ull acc[8][4];
    #pragma unroll
    for (int i = 0; i < 8; ++i)
        #pragma unroll
        for (int j = 0; j < 4; ++j) acc[i][j] = 0ull;

    for (int k0 = 0; k0 < K; k0 += 16){
        As[akq+0][ar] = ra0.x; As[akq+1][ar] = ra0.y;
        As[akq+2][ar] = ra0.z; As[akq+3][ar] = ra0.w;
        As[akq+0][64+ar] = ra1.x; As[akq+1][64+ar] = ra1.y;
        As[akq+2][64+ar] = ra1.z; As[akq+3][64+ar] = ra1.w;
        *reinterpret_cast<float4*>(&Bs[bkk][bnc])     = rb0;
        *reinterpret_cast<float4*>(&Bs[bkk][64+bnc])  = rb1;
        __syncthreads();
        if (k0 + 16 < K){
            ra0 = *reinterpret_cast<const float4*>(Ap0 + k0 + 16);
            ra1 = *reinterpret_cast<const float4*>(Ap1 + k0 + 16);
            rb0 = *reinterpret_cast<const float4*>(Bp0 + (size_t)(k0+16)*N);
            rb1 = *reinterpret_cast<const float4*>(Bp1 + (size_t)(k0+16)*N);
        }
        #pragma unroll
        for (int kk = 0; kk < 16; ++kk)
            INNER_KK(As[kk], Bs[kk], acc)
        __syncthreads();
    }

    // epilogue: bias + gelu; col groups n0 + j*32 + 2*tx
    float2 bb[4];
    #pragma unroll
    for (int j = 0; j < 4; ++j)
        bb[j] = *reinterpret_cast<const float2*>(&bias[n0 + j*32 + 2*tx]);
    #pragma unroll
    for (int mi = 0; mi < 8; ++mi){
        const int row = m0 + ((mi < 4) ? (ty*4 + mi) : (64 + ty*4 + mi - 4));
        float* Crow = C + (size_t)row*N + n0 + 2*tx;
        #pragma unroll
        for (int j = 0; j < 4; ++j){
            float2 v = unpack2(acc[mi][j]);
            v.x = gelu1(v.x + bb[j].x);
            v.y = gelu1(v.y + bb[j].y);
            *reinterpret_cast<float2*>(Crow + j*32) = v;
        }
    }
}

// ---------------------------------------------------------------------------
// g2: BM=64, BN=128, BK=16, 128 threads, 8x8 micro. split-K=2 partials.
// grid = (512/128=4, 512/64=8, 4)  z: side = z&1, split s = z>>1.
// C = g_p2[side][s]; bias folded in s==0 epilogue only.
// ---------------------------------------------------------------------------
__global__ void __launch_bounds__(128)
g2_kernel(const float* __restrict__ h1v, const float* __restrict__ Wmv,
          const float* __restrict__ bmv,
          const float* __restrict__ h1a, const float* __restrict__ Wma,
          const float* __restrict__ bma)
{
    const int side = blockIdx.z & 1;
    const int s    = blockIdx.z >> 1;
    const float* A    = side ? h1a : h1v;
    const float* B    = side ? Wma : Wmv;
    const float* bias = side ? bma : bmv;
    float* C = &g_p2[side][s][0];
    const int ks = s * 1024;               // K chunk of 1024

    constexpr int A_HI = 32;
    __shared__ float As[16][68];           // [k][m], 68*4B 16B-aligned
    __shared__ float Bs[16][128];

    const int t  = threadIdx.x;
    const int tx = t & 15;
    const int ty = t >> 4;                 // 0..7
    const int m0 = blockIdx.y * 64;
    const int n0 = blockIdx.x * 128;

    const int ar  = t >> 2;                // 0..31
    const int akq = (t & 3) << 2;
    const float* Ap0 = A + (size_t)(m0 + ar)*HH + ks + akq;
    const float* Ap1 = Ap0 + (size_t)32*HH;
    const int bkk = t >> 5;                // 0..3
    const int bnc = (t & 31) << 2;         // 0..124
    const float* Bp = B + (size_t)(ks + bkk)*DD + n0 + bnc;

    float4 ra0 = *reinterpret_cast<const float4*>(Ap0);
    float4 ra1 = *reinterpret_cast<const float4*>(Ap1);
    float4 rb0 = *reinterpret_cast<const float4*>(Bp + (size_t)0*DD);
    float4 rb1 = *reinterpret_cast<const float4*>(Bp + (size_t)4*DD);
    float4 rb2 = *reinterpret_cast<const float4*>(Bp + (size_t)8*DD);
    float4 rb3 = *reinterpret_cast<const float4*>(Bp + (size_t)12*DD);

    ull acc[8][4];
    #pragma unroll
    for (int i = 0; i < 8; ++i)
        #pragma unroll
        for (int j = 0; j < 4; ++j) acc[i][j] = 0ull;

    for (int k0 = 0; k0 < 1024; k0 += 16){
        As[akq+0][ar] = ra0.x; As[akq+1][ar] = ra0.y;
        As[akq+2][ar] = ra0.z; As[akq+3][ar] = ra0.w;
        As[akq+0][32+ar] = ra1.x; As[akq+1][32+ar] = ra1.y;
        As[akq+2][32+ar] = ra1.z; As[akq+3][32+ar] = ra1.w;
        *reinterpret_cast<float4*>(&Bs[bkk   ][bnc]) = rb0;
        *reinterpret_cast<float4*>(&Bs[bkk+ 4][bnc]) = rb1;
        *reinterpret_cast<float4*>(&Bs[bkk+ 8][bnc]) = rb2;
        *reinterpret_cast<float4*>(&Bs[bkk+12][bnc]) = rb3;
        __syncthreads();
        if (k0 + 16 < 1024){
            ra0 = *reinterpret_cast<const float4*>(Ap0 + k0 + 16);
            ra1 = *reinterpret_cast<const float4*>(Ap1 + k0 + 16);
            rb0 = *reinterpret_cast<const float4*>(Bp + (size_t)(k0+16)*DD);
            rb1 = *reinterpret_cast<const float4*>(Bp + (size_t)(k0+20)*DD);
            rb2 = *reinterpret_cast<const float4*>(Bp + (size_t)(k0+24)*DD);
            rb3 = *reinterpret_cast<const float4*>(Bp + (size_t)(k0+28)*DD);
        }
        #pragma unroll
        for (int kk = 0; kk < 16; ++kk)
            INNER_KK(As[kk], Bs[kk], acc)
        __syncthreads();
    }

    #pragma unroll
    for (int mi = 0; mi < 8; ++mi){
        const int row = m0 + ((mi < 4) ? (ty*4 + mi) : (32 + ty*4 + mi - 4));
        float* Crow = C + (size_t)row*DD + n0 + 2*tx;
        #pragma unroll
        for (int j = 0; j < 4; ++j){
            float2 v = unpack2(acc[mi][j]);
            if (s == 0){
                const float2 bb = *reinterpret_cast<const float2*>(&bias[n0 + j*32 + 2*tx]);
                v.x += bb.x; v.y += bb.y;
            }
            *reinterpret_cast<float2*>(Crow + j*32) = v;
        }
    }
}

// ---------------------------------------------------------------------------
// g3: BM=64, BN=128, 128 threads, split-K=4 over K=1024 (the concat dim).
// A tile synthesized on load: comb[m][k] = p2[side][0] + p2[side][1]
// where side = k>=512.  grid = (4, 8, 4), z = split s; each s covers 256 k
// entirely within one side (s<2 -> v, s>=2 -> a).
// ---------------------------------------------------------------------------
__global__ void __launch_bounds__(128)
g3_kernel(const float* __restrict__ Wout)
{
    const int s     = blockIdx.z;
    const int side  = s >> 1;
    const int kbase = (s & 1) * 256;       // within-side k offset
    const float* P0 = &g_p2[side][0][0];
    const float* P1 = &g_p2[side][1][0];
    const float* B  = Wout + (size_t)(side*512 + kbase)*DD;
    float* C = &g_p3[s][0];

    constexpr int A_HI = 32;
    __shared__ float As[16][68];
    __shared__ float Bs[16][128];

    const int t  = threadIdx.x;
    const int tx = t & 15;
    const int ty = t >> 4;
    const int m0 = blockIdx.y * 64;
    const int n0 = blockIdx.x * 128;

    const int ar  = t >> 2;
    const int akq = (t & 3) << 2;
    const float* Pp00 = P0 + (size_t)(m0 + ar)*DD + kbase + akq;
    const float* Pp10 = P1 + (size_t)(m0 + ar)*DD + kbase + akq;
    const float* Pp01 = Pp00 + (size_t)32*DD;
    const float* Pp11 = Pp10 + (size_t)32*DD;
    const int bkk = t >> 5;
    const int bnc = (t & 31) << 2;
    const float* Bp = B + (size_t)bkk*DD + n0 + bnc;

    float4 ra0, ra1, rb0, rb1, rb2, rb3;
    {
        float4 u = *reinterpret_cast<const float4*>(Pp00);
        float4 w = *reinterpret_cast<const float4*>(Pp10);
        ra0 = make_float4(u.x+w.x, u.y+w.y, u.z+w.z, u.w+w.w);
        u = *reinterpret_cast<const float4*>(Pp01);
        w = *reinterpret_cast<const float4*>(Pp11);
        ra1 = make_float4(u.x+w.x, u.y+w.y, u.z+w.z, u.w+w.w);
    }
    rb0 = *reinterpret_cast<const float4*>(Bp + (size_t)0*DD);
    rb1 = *reinterpret_cast<const float4*>(Bp + (size_t)4*DD);
    rb2 = *reinterpret_cast<const float4*>(Bp + (size_t)8*DD);
    rb3 = *reinterpret_cast<const float4*>(Bp + (size_t)12*DD);

    ull acc[8][4];
    #pragma unroll
    for (int i = 0; i < 8; ++i)
        #pragma unroll
        for (int j = 0; j < 4; ++j) acc[i][j] = 0ull;

    for (int k0 = 0; k0 < 256; k0 += 16){
        As[akq+0][ar] = ra0.x; As[akq+1][ar] = ra0.y;
        As[akq+2][ar] = ra0.z; As[akq+3][ar] = ra0.w;
        As[akq+0][32+ar] = ra1.x; As[akq+1][32+ar] = ra1.y;
        As[akq+2][32+ar] = ra1.z; As[akq+3][32+ar] = ra1.w;
        *reinterpret_cast<float4*>(&Bs[bkk   ][bnc]) = rb0;
        *reinterpret_cast<float4*>(&Bs[bkk+ 4][bnc]) = rb1;
        *reinterpret_cast<float4*>(&Bs[bkk+ 8][bnc]) = rb2;
        *reinterpret_cast<float4*>(&Bs[bkk+12][bnc]) = rb3;
        __syncthreads();
        if (k0 + 16 < 256){
            float4 u = *reinterpret_cast<const float4*>(Pp00 + k0 + 16);
            float4 w = *reinterpret_cast<const float4*>(Pp10 + k0 + 16);
            ra0 = make_float4(u.x+w.x, u.y+w.y, u.z+w.z, u.w+w.w);
            u = *reinterpret_cast<const float4*>(Pp01 + k0 + 16);
            w = *reinterpret_cast<const float4*>(Pp11 + k0 + 16);
            ra1 = make_float4(u.x+w.x, u.y+w.y, u.z+w.z, u.w+w.w);
            rb0 = *reinterpret_cast<const float4*>(Bp + (size_t)(k0+16)*DD);
            rb1 = *reinterpret_cast<const float4*>(Bp + (size_t)(k0+20)*DD);
            rb2 = *reinterpret_cast<const float4*>(Bp + (size_t)(k0+24)*DD);
            rb3 = *reinterpret_cast<const float4*>(Bp + (size_t)(k0+28)*DD);
        }
        #pragma unroll
        for (int kk = 0; kk < 16; ++kk)
            INNER_KK(As[kk], Bs[kk], acc)
        __syncthreads();
    }

    #pragma unroll
    for (int mi = 0; mi < 8; ++mi){
        const int row = m0 + ((mi < 4) ? (ty*4 + mi) : (32 + ty*4 + mi - 4));
        float* Crow = C + (size_t)row*DD + n0 + 2*tx;
        #pragma unroll
        for (int j = 0; j < 4; ++j){
            float2 v = unpack2(acc[mi][j]);
            *reinterpret_cast<float2*>(Crow + j*32) = v;
        }
    }
}

// ---------------------------------------------------------------------------
// Final reduce: out = sum_s p3[s] + bout   (float4 granularity)
// ---------------------------------------------------------------------------
__global__ void __launch_bounds__(256)
reduce4_kernel(float* __restrict__ out, const float* __restrict__ bout)
{
    const int idx = blockIdx.x * 256 + threadIdx.x;       // float4 index
    const float4 q0 = reinterpret_cast<const float4*>(g_p3[0])[idx];
    const float4 q1 = reinterpret_cast<const float4*>(g_p3[1])[idx];
    const float4 q2 = reinterpret_cast<const float4*>(g_p3[2])[idx];
    const float4 q3 = reinterpret_cast<const float4*>(g_p3[3])[idx];
    const float4 bb = reinterpret_cast<const float4*>(bout)[idx & 127];
    float4 r;
    r.x = q0.x + q1.x + q2.x + q3.x + bb.x;
    r.y = q0.y + q1.y + q2.y + q3.y + bb.y;
    r.z = q0.z + q1.z + q2.z + q3.z + bb.z;
    r.w = q0.w + q1.w + q2.w + q3.w + bb.w;
    reinterpret_cast<float4*>(out)[idx] = r;
}

// ---------------------------------------------------------------------------
extern "C" void kernel_launch(void* const* d_in, const int* in_sizes, int n_in,
                              void* d_out, int out_size)
{
    (void)in_sizes; (void)n_in; (void)out_size;

    const float* x_v  = (const float*)d_in[0];
    const float* x_a  = (const float*)d_in[1];
    const float* W1v  = (const float*)d_in[2];
    const float* b1v  = (const float*)d_in[3];
    const float* W1a  = (const float*)d_in[4];
    const float* b1a  = (const float*)d_in[5];
    const float* Wmv  = (const float*)d_in[6];
    const float* bmv  = (const float*)d_in[7];
    const float* Wma  = (const float*)d_in[8];
    const float* bma  = (const float*)d_in[9];
    const float* Wout = (const float*)d_in[10];
    const float* bout = (const float*)d_in[11];
    float* out = (float*)d_out;

    float *xvw, *xaw, *h1v, *h1a;
    cudaGetSymbolAddress((void**)&xvw, g_xvw);
    cudaGetSymbolAddress((void**)&xaw, g_xaw);
    cudaGetSymbolAddress((void**)&h1v, g_h1v);
    cudaGetSymbolAddress((void**)&h1a, g_h1a);

    // 1) pairwise L1 distances -> weighted inputs
    dist_weight_dual<<<dim3(NTOK/4, BB, 2), 128>>>(x_v, x_a, xvw, xaw);

    // 2) h1 = gelu(xw @ W1 + b1): M=512, N=2048, K=512; 128 blocks
    gemm128_dual<<<dim3(HH/128, MM/128, 2), 256>>>(
        xvw, W1v, b1v, h1v,
        xaw, W1a, b1a, h1a,
        DD, HH);

    // 3) G2 split-K=2 partials (bias folded into split 0): 128 blocks
    g2_kernel<<<dim3(DD/128, MM/64, 4), 128>>>(h1v, Wmv, bmv, h1a, Wma, bma);

    // 4) G3 split-K=4 over concat dim, p2 summed in A-load: 128 blocks
    g3_kernel<<<dim3(DD/128, MM/64, 4), 128>>>(Wout);

    // 5) out = sum partials + bout
    reduce4_kernel<<<(MM*DD/4)/256, 256>>>(out, bout);
}

// round 4
// speedup vs baseline: 2.1934x; 1.3105x over previous
#include <cuda_runtime.h>
#include <cuda_bf16.h>
#include <cstdint>

#define BB 2
#define NTOK 256
#define DD 512
#define HH 2048
#define MM (BB*NTOK)   /* 512 rows total */

typedef unsigned long long ull;

// ---------------- scratch (device globals: allocation-free) ----------------
__device__ __nv_bfloat16 g_xwhi[2*MM*DD],  g_xwlo[2*MM*DD];     // [side][m][k]
__device__ __nv_bfloat16 g_w1thi[2*HH*DD], g_w1tlo[2*HH*DD];    // [side][n=2048][k=512]
__device__ __nv_bfloat16 g_wmthi[2*DD*HH], g_wmtlo[2*DD*HH];    // [side][n=512][k=2048]
__device__ __nv_bfloat16 g_wothi[DD*2*DD], g_wotlo[DD*2*DD];    // [n=512][k=1024]
__device__ __nv_bfloat16 g_h1hi[2*MM*HH],  g_h1lo[2*MM*HH];     // [side][m][k=2048]
__device__ float         g_p2[8*MM*DD];                         // [side*4+sp][m][n]
__device__ __nv_bfloat16 g_combhi[MM*2*DD], g_comblo[MM*2*DD];  // [m][k=1024]
__device__ float         g_p3[8*MM*DD];                         // [sp][m][n]

// ---------------- helpers ----------------
__device__ __forceinline__ uint32_t smem_u32(const void* p){
    uint32_t a;
    asm("{ .reg .u64 t; cvta.to.shared.u64 t, %1; cvt.u32.u64 %0, t; }" : "=r"(a) : "l"(p));
    return a;
}
__device__ __forceinline__ ull addx2(ull a, ull b){
    ull d; asm("add.rn.f32x2 %0, %1, %2;" : "=l"(d) : "l"(a), "l"(b)); return d;
}
__device__ __forceinline__ float2 unpk2(ull v){
    uint32_t lo, hi;
    asm("mov.b64 {%0, %1}, %2;" : "=r"(lo), "=r"(hi) : "l"(v));
    return make_float2(__uint_as_float(lo), __uint_as_float(hi));
}
__device__ __forceinline__ void split_bf16(float v, __nv_bfloat16& h, __nv_bfloat16& l){
    h = __float2bfloat16(v);
    l = __float2bfloat16(v - __bfloat162float(h));
}
__device__ __forceinline__ float gelu1(float x){
    return 0.5f*x*(1.0f + erff(x*0.70710678118654752f));
}

// ---------------- cp.async / ldmatrix / mma (all baseline sm_80+ PTX) ------
__device__ __forceinline__ void cp16(uint32_t s, const void* g){
    asm volatile("cp.async.ca.shared.global [%0], [%1], 16;" :: "r"(s), "l"(g) : "memory");
}
#define CP_COMMIT() asm volatile("cp.async.commit_group;" ::: "memory")
#define CP_WAIT1()  asm volatile("cp.async.wait_group 1;" ::: "memory")
#define CP_WAIT0()  asm volatile("cp.async.wait_group 0;" ::: "memory")

#define LDM4(r, addr) \
    asm volatile("ldmatrix.sync.aligned.m8n8.x4.shared.b16 {%0,%1,%2,%3}, [%4];" \
        : "=r"((r)[0]), "=r"((r)[1]), "=r"((r)[2]), "=r"((r)[3]) : "r"(addr))
#define LDM2(r, addr) \
    asm volatile("ldmatrix.sync.aligned.m8n8.x2.shared.b16 {%0,%1}, [%2];" \
        : "=r"((r)[0]), "=r"((r)[1]) : "r"(addr))

#define MMA_BF16(d, a, b) \
    asm volatile("mma.sync.aligned.m16n8k16.row.col.f32.bf16.bf16.f32 " \
        "{%0,%1,%2,%3}, {%4,%5,%6,%7}, {%8,%9}, {%0,%1,%2,%3};" \
        : "+f"((d)[0]), "+f"((d)[1]), "+f"((d)[2]), "+f"((d)[3]) \
        : "r"((a)[0]), "r"((a)[1]), "r"((a)[2]), "r"((a)[3]), \
          "r"((b)[0]), "r"((b)[1]))

// Smem stage layout: 4 tiles of [128 rows][40 bf16] (80B rows, pad keeps
// ldmatrix conflict-free: 8 rows * 80B hit distinct 16B slots mod 128B).
#define ROWB   80
#define TILE_B (128*ROWB)      /* 10240 */
#define STAGE_B (4*TILE_B)     /* 40960 */
#define SMEM_BYTES (2*STAGE_B) /* 81920 */

// ---------------------------------------------------------------------------
// issue cp.async loads for one stage (BK=32 of all 4 tiles)
// thread t: row = t>>1, 32B half = t&1  (64B of bf16 payload per row)
// ---------------------------------------------------------------------------
__device__ __forceinline__ void issue_stage(
    uint32_t sb,
    const __nv_bfloat16* __restrict__ Ah, const __nv_bfloat16* __restrict__ Al, int lda,
    const __nv_bfloat16* __restrict__ Bh, const __nv_bfloat16* __restrict__ Bl, int ldb,
    int k0, int t)
{
    const int row  = t >> 1;
    const int half = t & 1;
    const uint32_t so = (uint32_t)(row*ROWB + half*32);
    const size_t ga = (size_t)row*lda + k0 + half*16;
    const size_t gb = (size_t)row*ldb + k0 + half*16;
    cp16(sb + so,                Ah + ga); cp16(sb + so + 16,                Ah + ga + 8);
    cp16(sb + TILE_B   + so,     Al + ga); cp16(sb + TILE_B   + so + 16,     Al + ga + 8);
    cp16(sb + 2*TILE_B + so,     Bh + gb); cp16(sb + 2*TILE_B + so + 16,     Bh + gb + 8);
    cp16(sb + 3*TILE_B + so,     Bl + gb); cp16(sb + 3*TILE_B + so + 16,     Bl + gb + 8);
}

// ---------------------------------------------------------------------------
// compute one BK=32 stage: 2 k16 steps, 3-term split-bf16 mma
// warp grid 2(m) x 4(n): warp tile 64x32 = 4x4 mma tiles of 16x8
// ---------------------------------------------------------------------------
__device__ __forceinline__ void compute_stage(
    uint32_t sb, int warp_m, int warp_n, int lane, float acc[4][4][4])
{
    const int arow = lane & 15;
    const int acol = (lane >> 4) * 8;
    const int brow = lane & 7;
    const int bcol = ((lane >> 3) & 1) * 8;

    #pragma unroll
    for (int kk = 0; kk < 32; kk += 16){
        uint32_t ah[4][4], al[4][4], bh[4][2], bl[4][2];
        #pragma unroll
        for (int mt = 0; mt < 4; ++mt){
            const uint32_t ao = (uint32_t)((warp_m*64 + mt*16 + arow)*ROWB + (kk + acol)*2);
            LDM4(ah[mt], sb + ao);
            LDM4(al[mt], sb + TILE_B + ao);
        }
        #pragma unroll
        for (int nt = 0; nt < 4; ++nt){
            const uint32_t bo = (uint32_t)((warp_n*32 + nt*8 + brow)*ROWB + (kk + bcol)*2);
            LDM2(bh[nt], sb + 2*TILE_B + bo);
            LDM2(bl[nt], sb + 3*TILE_B + bo);
        }
        // term order keeps 16 independent mmas between same-acc repeats
        #pragma unroll
        for (int mt = 0; mt < 4; ++mt)
            #pragma unroll
            for (int nt = 0; nt < 4; ++nt)
                MMA_BF16(acc[mt][nt], ah[mt], bh[nt]);
        #pragma unroll
        for (int mt = 0; mt < 4; ++mt)
            #pragma unroll
            for (int nt = 0; nt < 4; ++nt)
                MMA_BF16(acc[mt][nt], ah[mt], bl[nt]);
        #pragma unroll
        for (int mt = 0; mt < 4; ++mt)
            #pragma unroll
            for (int nt = 0; nt < 4; ++nt)
                MMA_BF16(acc[mt][nt], al[mt], bh[nt]);
    }
}

// ---------------------------------------------------------------------------
// GEMM core: acc[4][4][4] = A[128,K] @ B^T[128,K]  (128x128 CTA tile)
// ---------------------------------------------------------------------------
__device__ __forceinline__ void gemm_mma(
    const __nv_bfloat16* __restrict__ Ah, const __nv_bfloat16* __restrict__ Al, int lda,
    const __nv_bfloat16* __restrict__ Bh, const __nv_bfloat16* __restrict__ Bl, int ldb,
    int K, float acc[4][4][4], char* smem)
{
    const uint32_t sb = smem_u32(smem);
    const int t = threadIdx.x;
    const int lane = t & 31, wid = t >> 5;
    const int warp_m = wid & 1, warp_n = wid >> 1;

    #pragma unroll
    for (int i = 0; i < 4; ++i)
        #pragma unroll
        for (int j = 0; j < 4; ++j)
            #pragma unroll
            for (int r = 0; r < 4; ++r) acc[i][j][r] = 0.0f;

    const int nIter = K >> 5;
    issue_stage(sb, Ah, Al, lda, Bh, Bl, ldb, 0, t);
    CP_COMMIT();

    for (int it = 0; it < nIter; ++it){
        if (it + 1 < nIter){
            issue_stage(sb + ((it+1)&1)*STAGE_B, Ah, Al, lda, Bh, Bl, ldb, (it+1)*32, t);
            CP_COMMIT();
            CP_WAIT1();
        } else {
            CP_WAIT0();
        }
        __syncthreads();
        compute_stage(sb + (it&1)*STAGE_B, warp_m, warp_n, lane, acc);
        __syncthreads();
    }
}

// ---------------------------------------------------------------------------
// Distance + weighting: dv/da means, weighted x -> bf16 hi/lo split output.
// ---------------------------------------------------------------------------
__global__ void __launch_bounds__(256)
dist_weight_dual(const float* __restrict__ xv, const float* __restrict__ xa)
{
    const int dir = blockIdx.z;
    const float* self  = dir ? xa : xv;
    const float* other = dir ? xv : xa;
    __nv_bfloat16* ohi = g_xwhi + (size_t)dir*MM*DD;
    __nv_bfloat16* olo = g_xwlo + (size_t)dir*MM*DD;

    const int b  = blockIdx.y;
    const int i0 = blockIdx.x * 8;
    const int t  = threadIdx.x;               // owns dims 2t, 2t+1

    const ull* sb_ = reinterpret_cast<const ull*>(self  + (size_t)b*NTOK*DD);
    const ull* ob_ = reinterpret_cast<const ull*>(other + (size_t)b*NTOK*DD);

    ull a[8], acc[8];
    #pragma unroll
    for (int r = 0; r < 8; ++r){
        a[r] = sb_[(size_t)(i0+r)*256 + t];
        acc[r] = 0ull;
    }
    const ull SGN = 0x8000000080000000ull;
    const ull ABS = 0x7FFFFFFF7FFFFFFFull;

    #pragma unroll 2
    for (int j = 0; j < NTOK; ++j){
        const ull on = ob_[(size_t)j*256 + t] ^ SGN;   // -other
        #pragma unroll
        for (int r = 0; r < 8; ++r){
            ull d = addx2(a[r], on);
            d &= ABS;
            acc[r] = addx2(acc[r], d);
        }
    }

    __shared__ float red[8][256];
    #pragma unroll
    for (int r = 0; r < 8; ++r){
        float2 p = unpk2(acc[r]);
        red[r][t] = p.x + p.y;
    }
    __syncthreads();
    for (int s = 128; s > 0; s >>= 1){
        if (t < s){
            #pragma unroll
            for (int r = 0; r < 8; ++r) red[r][t] += red[r][t+s];
        }
        __syncthreads();
    }

    const float inv = 1.0f / (float)NTOK;
    #pragma unroll
    for (int r = 0; r < 8; ++r){
        const float s = red[r][0] * inv;
        const float2 av = unpk2(a[r]);
        const float v0 = av.x * s, v1 = av.y * s;
        __nv_bfloat16 h0, l0, h1, l1;
        split_bf16(v0, h0, l0);
        split_bf16(v1, h1, l1);
        __nv_bfloat162 ph; ph.x = h0; ph.y = h1;
        __nv_bfloat162 pl; pl.x = l0; pl.y = l1;
        const size_t o = (size_t)(b*NTOK + i0 + r)*DD + 2*t;
        *reinterpret_cast<__nv_bfloat162*>(ohi + o) = ph;
        *reinterpret_cast<__nv_bfloat162*>(olo + o) = pl;
    }
}

// ---------------------------------------------------------------------------
// Weight transpose + bf16 split: src[R][C] -> dst_hi/lo[C][R].
// ---------------------------------------------------------------------------
__global__ void __launch_bounds__(256)
transpose_split(const float* __restrict__ W1v, const float* __restrict__ W1a,
                const float* __restrict__ Wmv, const float* __restrict__ Wma,
                const float* __restrict__ Wout)
{
    const int bid = blockIdx.x;
    const float* src; __nv_bfloat16 *dhi, *dlo; int R, C, ti;
    if (bid < 1024)      { src=W1v;  dhi=g_w1thi;          dlo=g_w1tlo;          R=512;  C=2048; ti=bid; }
    else if (bid < 2048) { src=W1a;  dhi=g_w1thi+HH*DD;    dlo=g_w1tlo+HH*DD;    R=512;  C=2048; ti=bid-1024; }
    else if (bid < 3072) { src=Wmv;  dhi=g_wmthi;          dlo=g_wmtlo;          R=2048; C=512;  ti=bid-2048; }
    else if (bid < 4096) { src=Wma;  dhi=g_wmthi+DD*HH;    dlo=g_wmtlo+DD*HH;    R=2048; C=512;  ti=bid-3072; }
    else                 { src=Wout; dhi=g_wothi;          dlo=g_wotlo;          R=1024; C=512;  ti=bid-4096; }

    const int TC_ = C >> 5;
    const int c0 = (ti % TC_) * 32;
    const int r0 = (ti / TC_) * 32;

    __shared__ float s[32][33];
    const int tx = threadIdx.x & 31;
    const int ty = threadIdx.x >> 5;

    #pragma unroll
    for (int i = 0; i < 4; ++i)
        s[ty + 8*i][tx] = src[(size_t)(r0 + ty + 8*i)*C + c0 + tx];
    __syncthreads();

    #pragma unroll
    for (int i = 0; i < 4; ++i){
        const int cc = ty + 8*i;
        const float v = s[tx][cc];
        __nv_bfloat16 h, l;
        split_bf16(v, h, l);
        dhi[(size_t)(c0 + cc)*R + r0 + tx] = h;
        dlo[(size_t)(c0 + cc)*R + r0 + tx] = l;
    }
}

// ---------------------------------------------------------------------------
// G1: h1 = gelu(xw @ W1 + b1) -> bf16 hi/lo.  grid (16, 4, 2), 256 thr.
// ---------------------------------------------------------------------------
__global__ void __launch_bounds__(256)
g1_mma(const float* __restrict__ b1v, const float* __restrict__ b1a)
{
    extern __shared__ char smem[];
    const int side = blockIdx.z;
    const int n0 = blockIdx.x * 128, m0 = blockIdx.y * 128;

    const __nv_bfloat16* Ah = g_xwhi  + (size_t)side*MM*DD + (size_t)m0*DD;
    const __nv_bfloat16* Al = g_xwlo  + (size_t)side*MM*DD + (size_t)m0*DD;
    const __nv_bfloat16* Bh = g_w1thi + (size_t)side*HH*DD + (size_t)n0*DD;
    const __nv_bfloat16* Bl = g_w1tlo + (size_t)side*HH*DD + (size_t)n0*DD;

    float acc[4][4][4];
    gemm_mma(Ah, Al, DD, Bh, Bl, DD, DD, acc, smem);

    const float* bias = side ? b1a : b1v;
    __nv_bfloat16* Hh = g_h1hi + (size_t)side*MM*HH;
    __nv_bfloat16* Hl = g_h1lo + (size_t)side*MM*HH;

    const int lane = threadIdx.x & 31, wid = threadIdx.x >> 5;
    const int warp_m = wid & 1, warp_n = wid >> 1;

    #pragma unroll
    for (int mt = 0; mt < 4; ++mt){
        #pragma unroll
        for (int nt = 0; nt < 4; ++nt){
            const int row = m0 + warp_m*64 + mt*16 + (lane >> 2);
            const int col = n0 + warp_n*32 + nt*8  + (lane & 3)*2;
            const float bb0 = bias[col], bb1 = bias[col+1];
            #pragma unroll
            for (int h = 0; h < 2; ++h){
                const int rr = row + h*8;
                float v0 = gelu1(acc[mt][nt][2*h]   + bb0);
                float v1 = gelu1(acc[mt][nt][2*h+1] + bb1);
                __nv_bfloat16 h0, l0, h1, l1;
                split_bf16(v0, h0, l0);
                split_bf16(v1, h1, l1);
                __nv_bfloat162 ph; ph.x = h0; ph.y = h1;
                __nv_bfloat162 pl; pl.x = l0; pl.y = l1;
                *reinterpret_cast<__nv_bfloat162*>(Hh + (size_t)rr*HH + col) = ph;
                *reinterpret_cast<__nv_bfloat162*>(Hl + (size_t)rr*HH + col) = pl;
            }
        }
    }
}

// ---------------------------------------------------------------------------
// G2: p2[side][sp] = h1[:, sp*512:(sp+1)*512] @ WmT  (fp32 partials)
// grid (4, 4, 8): side = z&1, sp = z>>1.  K per split = 512.
// ---------------------------------------------------------------------------
__global__ void __launch_bounds__(256)
g2_mma()
{
    extern __shared__ char smem[];
    const int side = blockIdx.z & 1;
    const int sp   = blockIdx.z >> 1;
    const int n0 = blockIdx.x * 128, m0 = blockIdx.y * 128;
    const int ko = sp * 512;

    const __nv_bfloat16* Ah = g_h1hi  + (size_t)side*MM*HH + (size_t)m0*HH + ko;
    const __nv_bfloat16* Al = g_h1lo  + (size_t)side*MM*HH + (size_t)m0*HH + ko;
    const __nv_bfloat16* Bh = g_wmthi + (size_t)side*DD*HH + (size_t)n0*HH + ko;
    const __nv_bfloat16* Bl = g_wmtlo + (size_t)side*DD*HH + (size_t)n0*HH + ko;

    float acc[4][4][4];
    gemm_mma(Ah, Al, HH, Bh, Bl, HH, 512, acc, smem);

    float* C = g_p2 + (size_t)(side*4 + sp)*MM*DD;
    const int lane = threadIdx.x & 31, wid = threadIdx.x >> 5;
    const int warp_m = wid & 1, warp_n = wid >> 1;

    #pragma unroll
    for (int mt = 0; mt < 4; ++mt){
        #pragma unroll
        for (int nt = 0; nt < 4; ++nt){
            const int row = m0 + warp_m*64 + mt*16 + (lane >> 2);
            const int col = n0 + warp_n*32 + nt*8  + (lane & 3)*2;
            #pragma unroll
            for (int h = 0; h < 2; ++h){
                *reinterpret_cast<float2*>(C + (size_t)(row + h*8)*DD + col) =
                    make_float2(acc[mt][nt][2*h], acc[mt][nt][2*h+1]);
            }
        }
    }
}

// ---------------------------------------------------------------------------
// Reduce G2 partials + bias -> comb bf16 hi/lo.
// ---------------------------------------------------------------------------
__global__ void __launch_bounds__(256)
reduce_g2(const float* __restrict__ bmv, const float* __restrict__ bma)
{
    const int q = blockIdx.x * 256 + threadIdx.x;   // [0, 131072)
    const int n = (q & 255) * 4;                    // [0, 1024)
    const int m = q >> 8;                           // [0, 512)
    const int side = n >> 9;
    const int c = n & 511;

    const float* P = g_p2 + (size_t)side*4*MM*DD + (size_t)m*DD + c;
    float4 v0 = *reinterpret_cast<const float4*>(P);
    float4 v1 = *reinterpret_cast<const float4*>(P + MM*DD);
    float4 v2 = *reinterpret_cast<const float4*>(P + 2*MM*DD);
    float4 v3 = *reinterpret_cast<const float4*>(P + 3*MM*DD);
    const float* bias = side ? bma : bmv;
    float4 bb = *reinterpret_cast<const float4*>(bias + c);

    float v[4];
    v[0] = v0.x + v1.x + v2.x + v3.x + bb.x;
    v[1] = v0.y + v1.y + v2.y + v3.y + bb.y;
    v[2] = v0.z + v1.z + v2.z + v3.z + bb.z;
    v[3] = v0.w + v1.w + v2.w + v3.w + bb.w;

    const size_t o = (size_t)m*(2*DD) + n;
    #pragma unroll
    for (int i = 0; i < 4; i += 2){
        __nv_bfloat16 h0, l0, h1, l1;
        split_bf16(v[i],   h0, l0);
        split_bf16(v[i+1], h1, l1);
        __nv_bfloat162 ph; ph.x = h0; ph.y = h1;
        __nv_bfloat162 pl; pl.x = l0; pl.y = l1;
        *reinterpret_cast<__nv_bfloat162*>(g_combhi + o + i) = ph;
        *reinterpret_cast<__nv_bfloat162*>(g_comblo + o + i) = pl;
    }
}

// ---------------------------------------------------------------------------
// G3: p3[sp] = comb[:, sp*128:(sp+1)*128] @ WoutT  (fp32 partials)
// grid (4, 4, 8): z = sp, K per split = 128.
// ---------------------------------------------------------------------------
__global__ void __launch_bounds__(256)
g3_mma()
{
    extern __shared__ char smem[];
    const int sp = blockIdx.z;
    const int n0 = blockIdx.x * 128, m0 = blockIdx.y * 128;
    const int ko = sp * 128;

    const __nv_bfloat16* Ah = g_combhi + (size_t)m0*(2*DD) + ko;
    const __nv_bfloat16* Al = g_comblo + (size_t)m0*(2*DD) + ko;
    const __nv_bfloat16* Bh = g_wothi  + (size_t)n0*(2*DD) + ko;
    const __nv_bfloat16* Bl = g_wotlo  + (size_t)n0*(2*DD) + ko;

    float acc[4][4][4];
    gemm_mma(Ah, Al, 2*DD, Bh, Bl, 2*DD, 128, acc, smem);

    float* C = g_p3 + (size_t)sp*MM*DD;
    const int lane = threadIdx.x & 31, wid = threadIdx.x >> 5;
    const int warp_m = wid & 1, warp_n = wid >> 1;

    #pragma unroll
    for (int mt = 0; mt < 4; ++mt){
        #pragma unroll
        for (int nt = 0; nt < 4; ++nt){
            const int row = m0 + warp_m*64 + mt*16 + (lane >> 2);
            const int col = n0 + warp_n*32 + nt*8  + (lane & 3)*2;
            #pragma unroll
            for (int h = 0; h < 2; ++h){
                *reinterpret_cast<float2*>(C + (size_t)(row + h*8)*DD + col) =
                    make_float2(acc[mt][nt][2*h], acc[mt][nt][2*h+1]);
            }
        }
    }
}

// ---------------------------------------------------------------------------
// Reduce G3 partials + bout -> out fp32.
// ---------------------------------------------------------------------------
__global__ void __launch_bounds__(256)
reduce_g3(float* __restrict__ out, const float* __restrict__ bout)
{
    const int q = blockIdx.x * 256 + threadIdx.x;   // [0, 65536)
    const int n = (q & 127) * 4;
    const int m = q >> 7;
    const size_t o = (size_t)m*DD + n;

    float4 r = *reinterpret_cast<const float4*>(bout + n);
    #pragma unroll
    for (int sp = 0; sp < 8; ++sp){
        float4 v = *reinterpret_cast<const float4*>(g_p3 + (size_t)sp*MM*DD + o);
        r.x += v.x; r.y += v.y; r.z += v.z; r.w += v.w;
    }
    *reinterpret_cast<float4*>(out + o) = r;
}

// ---------------------------------------------------------------------------
extern "C" void kernel_launch(void* const* d_in, const int* in_sizes, int n_in,
                              void* d_out, int out_size)
{
    (void)in_sizes; (void)n_in; (void)out_size;

    const float* x_v  = (const float*)d_in[0];
    const float* x_a  = (const float*)d_in[1];
    const float* W1v  = (const float*)d_in[2];
    const float* b1v  = (const float*)d_in[3];
    const float* W1a  = (const float*)d_in[4];
    const float* b1a  = (const float*)d_in[5];
    const float* Wmv  = (const float*)d_in[6];
    const float* bmv  = (const float*)d_in[7];
    const float* Wma  = (const float*)d_in[8];
    const float* bma  = (const float*)d_in[9];
    const float* Wout = (const float*)d_in[10];
    const float* bout = (const float*)d_in[11];
    float* out = (float*)d_out;

    cudaFuncSetAttribute(g1_mma, cudaFuncAttributeMaxDynamicSharedMemorySize, SMEM_BYTES);
    cudaFuncSetAttribute(g2_mma, cudaFuncAttributeMaxDynamicSharedMemorySize, SMEM_BYTES);
    cudaFuncSetAttribute(g3_mma, cudaFuncAttributeMaxDynamicSharedMemorySize, SMEM_BYTES);

    // 1) weight transpose + bf16 split
    transpose_split<<<4608, 256>>>(W1v, W1a, Wmv, Wma, Wout);

    // 2) pairwise L1 distances -> weighted inputs (bf16 hi/lo)
    dist_weight_dual<<<dim3(NTOK/8, BB, 2), 256>>>(x_v, x_a);

    // 3) G1: h1 = gelu(xw @ W1 + b1) -> bf16 split
    g1_mma<<<dim3(HH/128, MM/128, 2), 256, SMEM_BYTES>>>(b1v, b1a);

    // 4) G2: split-K=4 partials per side
    g2_mma<<<dim3(DD/128, MM/128, 8), 256, SMEM_BYTES>>>();

    // 5) comb = sum partials + bias -> bf16 split
    reduce_g2<<<512, 256>>>(bmv, bma);

    // 6) G3: split-K=8 partials
    g3_mma<<<dim3(DD/128, MM/128, 8), 256, SMEM_BYTES>>>();

    // 7) out = sum partials + bout
    reduce_g3<<<256, 256>>>(out, bout);
}